// round 15
// baseline (speedup 1.0000x reference)
#include <cuda_runtime.h>

// Problem constants
#define BATCH   4
#define NPTS    16384
#define HALF    8192
#define FDIM    32
#define GD      16               // cells per axis (in CDF/u-space)
#define NC      (GD*GD*GD)       // 4096 cells per batch

typedef unsigned int u32;
typedef unsigned long long u64;

// Output layout (concatenated tuple, float32)
#define OFF_VPC   0
#define OFF_VFEAT (BATCH * HALF * 3)                  // 98304
#define OFF_NIDX  (OFF_VFEAT + BATCH * HALF * FDIM)   // 1146880
#define OFF_RNDS  (OFF_NIDX + BATCH * HALF)           // 1179648

// Cell boundaries in x-space: standard normal quantiles Phi^-1(i/16).
__constant__ float c_bnd[GD + 1] = {
    -1e30f,
    -1.5341206f, -1.1503494f, -0.8871466f, -0.6744898f,
    -0.4887764f, -0.3186394f, -0.1573107f,  0.0f,
     0.1573107f,  0.3186394f,  0.4887764f,  0.6744898f,
     0.8871466f,  1.1503494f,  1.5341206f,
     1e30f
};

// ---------------------------------------------------------------------------
// Scratch (device globals). Zero-initialized at module load; g_cnt re-zeroed
// by knn_kernel's tail each run (graph replays).
// ---------------------------------------------------------------------------
__device__ float4 g_valid[BATCH][HALF];
__device__ float4 g_query[BATCH][HALF];
__device__ int    g_pcell[BATCH][HALF];
__device__ int    g_qcell[BATCH][HALF];
__device__ int    g_cnt[2][BATCH][NC];
__device__ int    g_off[2][BATCH][NC+1];
__device__ int    g_cur[2][BATCH][NC];
__device__ float4 g_spt[BATCH][HALF];     // cell-sorted points (2x,2y,2z,p2)
__device__ int    g_sid[BATCH][HALF];     // original point index
__device__ float4 g_sq[BATCH][HALF];      // cell-sorted queries (x,y,z,q2)
__device__ int    g_sqid[BATCH][HALF];
__device__ int    g_sqc[BATCH][HALF];

// ||v||^2 left-to-right, no FMA contraction (match jax fp32 semantics)
__device__ __forceinline__ float sq3(float x, float y, float z) {
    return __fadd_rn(__fadd_rn(__fmul_rn(x, x), __fmul_rn(y, y)), __fmul_rn(z, z));
}

__device__ __forceinline__ int axis_cell(float x) {
    float u = __fmaf_rn(erff(x * 0.70710678f), 0.5f, 0.5f);
    int c = (int)(u * (float)GD);
    return max(0, min(GD - 1, c));
}
__device__ __forceinline__ int cell_of(float x, float y, float z) {
    return (axis_cell(z) * GD + axis_cell(y)) * GD + axis_cell(x);
}

// Order-preserving float->u32 encode (monotone incl. +inf)
__device__ __forceinline__ u32 fenc32(float f) {
    u32 u = __float_as_uint(f);
    return u ^ ((u32)((int)u >> 31) | 0x80000000u);
}
__device__ __forceinline__ float fdec32(u32 e) {
    return __uint_as_float((e & 0x80000000u) ? (e ^ 0x80000000u) : ~e);
}

__device__ __forceinline__ bool lt2(float d, int i, float e, int j) {
    return d < e || (d == e && i < j);
}

// Insert candidate (d, i) into per-lane sorted top-2, deduping by id.
__device__ __forceinline__ void ins2(float d, int i,
                                     float& bd1, int& bi1,
                                     float& bd2, int& bi2) {
    if (i == bi1 || i == bi2) return;
    if (lt2(d, i, bd1, bi1)) {
        bd2 = bd1; bi2 = bi1; bd1 = d; bi1 = i;
    } else if (lt2(d, i, bd2, bi2)) {
        bd2 = d; bi2 = i;
    }
}

// Final exact top-2 via u64 keys (R9-proven): key=(enc(d)<<32)|id; u64 order
// == stable top_k comparator; same id => identical key => dedup by equality.
#define KINF (((u64)0xFF800000u << 32) | 0xFFFFFFFFu)
__device__ __forceinline__ void warp_reduce_top2k(u64& k1, u64& k2) {
    u64 k1g = k1;
#pragma unroll
    for (int o = 16; o > 0; o >>= 1)
        k1g = min(k1g, __shfl_xor_sync(0xFFFFFFFFu, k1g, o));
    u64 cand = (k1 == k1g) ? k2 : k1;
#pragma unroll
    for (int o = 16; o > 0; o >>= 1)
        cand = min(cand, __shfl_xor_sync(0xFFFFFFFFu, cand, o));
    k1 = k1g; k2 = cand;
}

// Cheap conservative UPPER bound on global bd2 via 2x hardware REDUX (safe:
// equal-distance collisions only raise it).
__device__ __forceinline__ float warp_ub2(float bd1, float bd2) {
    u32 e1 = fenc32(bd1);
    u32 m1 = __reduce_min_sync(0xFFFFFFFFu, e1);
    u32 c = (e1 == m1) ? fenc32(bd2) : e1;
    u32 m2 = __reduce_min_sync(0xFFFFFFFFu, c);
    return fdec32(m2);
}

__device__ __forceinline__ float score(float qx, float qy, float qz, float q2,
                                       float4 P) {
    float dot2 = __fadd_rn(__fadd_rn(__fmul_rn(qx, P.x), __fmul_rn(qy, P.y)),
                           __fmul_rn(qz, P.z));
    return __fsub_rn(__fadd_rn(q2, P.w), dot2);
}

// ---------------------------------------------------------------------------
// K1 (launch 0): gathers + binning + histogram
// ---------------------------------------------------------------------------
__global__ void gather_kernel(const float* __restrict__ pc,
                              const float4* __restrict__ feats4,
                              const int* __restrict__ rnds,
                              float* __restrict__ out) {
    int i = blockIdx.x * blockDim.x + threadIdx.x;
    const int WF = BATCH * HALF * 8;
    const int WP = BATCH * HALF;

    if (i < WF) {
        int c = i & 7;
        int t = (i >> 3) & (HALF - 1);
        int b = i >> 16;
        int v = rnds[t];
        float4 val = feats4[(b * NPTS + v) * 8 + c];
        ((float4*)(out + OFF_VFEAT))[(b * HALF + t) * 8 + c] = val;
        return;
    }
    i -= WF;
    if (i < WP) {
        int t = i & (HALF - 1);
        int b = i >> 13;
        int v = rnds[t];
        int base = (b * NPTS + v) * 3;
        float x = pc[base + 0], y = pc[base + 1], z = pc[base + 2];
        int ob = OFF_VPC + (b * HALF + t) * 3;
        out[ob + 0] = x; out[ob + 1] = y; out[ob + 2] = z;
        g_valid[b][t] = make_float4(2.0f * x, 2.0f * y, 2.0f * z, sq3(x, y, z));
        int cid = cell_of(x, y, z);
        g_pcell[b][t] = cid;
        atomicAdd(&g_cnt[0][b][cid], 1);
        return;
    }
    i -= WP;
    if (i < WP) {
        int t = i & (HALF - 1);
        int b = i >> 13;
        int v = rnds[HALF + t];
        int base = (b * NPTS + v) * 3;
        float x = pc[base + 0], y = pc[base + 1], z = pc[base + 2];
        g_query[b][t] = make_float4(x, y, z, sq3(x, y, z));
        int cid = cell_of(x, y, z);
        g_qcell[b][t] = cid;
        atomicAdd(&g_cnt[1][b][cid], 1);
        return;
    }
    i -= WP;
    if (i < NPTS) out[OFF_RNDS + i] = (float)rnds[i];
}

// ---------------------------------------------------------------------------
// K2 (launch 1): exclusive scan via two-level warp shuffle scan
// ---------------------------------------------------------------------------
__global__ void __launch_bounds__(1024) scan_kernel() {
    int kind = blockIdx.x >> 2;
    int b = blockIdx.x & 3;
    const int CPT = NC / 1024;  // 4
    int tid = threadIdx.x;
    int lane = tid & 31;
    int wid = tid >> 5;

    int loc[CPT];
    int s = 0;
    const int* cnt = g_cnt[kind][b];
#pragma unroll
    for (int j = 0; j < CPT; ++j) { loc[j] = s; s += cnt[tid * CPT + j]; }

    int inc = s;
#pragma unroll
    for (int o = 1; o < 32; o <<= 1) {
        int v = __shfl_up_sync(0xFFFFFFFFu, inc, o);
        if (lane >= o) inc += v;
    }
    __shared__ int wsum[32];
    if (lane == 31) wsum[wid] = inc;
    __syncthreads();
    if (wid == 0) {
        int v = wsum[lane];
        int wi = v;
#pragma unroll
        for (int o = 1; o < 32; o <<= 1) {
            int u = __shfl_up_sync(0xFFFFFFFFu, wi, o);
            if (lane >= o) wi += u;
        }
        wsum[lane] = wi - v;
    }
    __syncthreads();
    int base = wsum[wid] + (inc - s);

    int* off_arr = g_off[kind][b];
    int* cur_arr = g_cur[kind][b];
#pragma unroll
    for (int j = 0; j < CPT; ++j) {
        int v = base + loc[j];
        off_arr[tid * CPT + j] = v;
        cur_arr[tid * CPT + j] = v;
    }
    if (tid == 1023) off_arr[NC] = base + s;
}

// ---------------------------------------------------------------------------
// K3 (launch 2): scatter into cell-sorted order
// ---------------------------------------------------------------------------
__global__ void scatter_kernel() {
    int i = blockIdx.x * blockDim.x + threadIdx.x;
    if (i >= 2 * BATCH * HALF) return;
    int kind = i >> 15;
    int b = (i >> 13) & (BATCH - 1);
    int t = i & (HALF - 1);
    if (kind == 0) {
        int cid = g_pcell[b][t];
        int pos = atomicAdd(&g_cur[0][b][cid], 1);
        g_spt[b][pos] = g_valid[b][t];
        g_sid[b][pos] = t;
    } else {
        int cid = g_qcell[b][t];
        int pos = atomicAdd(&g_cur[1][b][cid], 1);
        g_sq[b][pos] = g_query[b][t];
        g_sqid[b][pos] = t;
        g_sqc[b][pos] = cid;
    }
}

// ---------------------------------------------------------------------------
// K4 (launch 3 — ncu slot): warp-per-query KNN, serial-run broadcast version.
// NO flat-index binary search, NO length scan: runs (merged x-rows) are
// iterated serially; (p0, len) broadcast from owning lane (independent shfls
// => pipelined); lanes < len score pts[p0+lane] directly. Phase 1 = adaptive
// 4x4x4 window (16 runs, ~95% term). Phase 2 = 5x5x5 box (25 runs; id-dedup
// makes overlap harmless). Phase 3 = bounded brute force. Termination via
// REDUX ub2 (conservative). Final exact top-2 via u64-key reduce. Scoring
// formula exact => bit-identical to reference.
// ---------------------------------------------------------------------------
__device__ __forceinline__ void scan_runs(int x0, int x1, int y0, int NYW,
                                          int z0, int NR,
                                          float qx, float qy, float qz, float q2,
                                          const float4* __restrict__ pts,
                                          const int* __restrict__ ids,
                                          const int* __restrict__ offs,
                                          int lane,
                                          float& bd1, int& bi1,
                                          float& bd2, int& bi2) {
    // lane r owns run r: (cy, cz) = (y0 + r%NYW, z0 + r/NYW); len=0 if OOB
    int p0 = 0, len = 0;
    if (lane < NR) {
        int cy = y0 + lane % NYW;
        int cz = z0 + lane / NYW;
        if (cy >= 0 && cy < GD && cz >= 0 && cz < GD) {
            int rowbase = (cz * GD + cy) * GD;
            p0 = __ldg(&offs[rowbase + x0]);
            len = __ldg(&offs[rowbase + x1 + 1]) - p0;
        }
    }
    // serial-run broadcast: each iteration's shfls are independent => overlap
    for (int r = 0; r < NR; ++r) {
        int rp = __shfl_sync(0xFFFFFFFFu, p0, r);
        int rl = __shfl_sync(0xFFFFFFFFu, len, r);
        for (int j = lane; j < rl; j += 32) {
            float4 P = pts[rp + j];
            float d2 = score(qx, qy, qz, q2, P);
            if (d2 <= bd2) ins2(d2, ids[rp + j], bd1, bi1, bd2, bi2);
        }
    }
}

// warp-uniform: can any cell outside window [x0..x1]x[y0..y1]x[z0..z1] beat ub2?
__device__ __forceinline__ bool term_ok_w(int x0, int x1, int y0, int y1,
                                          int z0, int z1,
                                          float qx, float qy, float qz,
                                          float ub2) {
    const float INF = __int_as_float(0x7f800000);
    if (!(ub2 < INF)) return false;
    float lb = INF;
    if (x0 > 0)      lb = fminf(lb, qx - c_bnd[x0]);
    if (x1 < GD - 1) lb = fminf(lb, c_bnd[x1 + 1] - qx);
    if (y0 > 0)      lb = fminf(lb, qy - c_bnd[y0]);
    if (y1 < GD - 1) lb = fminf(lb, c_bnd[y1 + 1] - qy);
    if (z0 > 0)      lb = fminf(lb, qz - c_bnd[z0]);
    if (z1 < GD - 1) lb = fminf(lb, c_bnd[z1 + 1] - qz);
    float lba = fmaxf(lb - 1e-5f, 0.0f);
    return lba * lba > ub2 * 1.001f + 1e-4f;
}

__global__ void __launch_bounds__(256) knn_kernel(float* __restrict__ out) {
    int w = (blockIdx.x * blockDim.x + threadIdx.x) >> 5;
    int lane = threadIdx.x & 31;
    int b = w >> 13;
    int s = w & (HALF - 1);

    float4 q = g_sq[b][s];
    int qi = g_sqid[b][s];
    int qc = g_sqc[b][s];
    const float qx = q.x, qy = q.y, qz = q.z, q2 = q.w;

    int qcx = qc & (GD - 1);
    int qcy = (qc >> 4) & (GD - 1);
    int qcz = qc >> 8;

    const float INF = __int_as_float(0x7f800000);
    float bd1 = INF, bd2 = INF;
    int bi1 = 0x7fffffff, bi2 = 0x7fffffff;

    const float4* __restrict__ pts = g_spt[b];
    const int* __restrict__ ids = g_sid[b];
    const int* __restrict__ offs = g_off[0][b];

    // Phase 1: query-adaptive 4x4x4 window (centered on query within cell)
    bool lowx = (qx - c_bnd[qcx]) < (c_bnd[qcx + 1] - qx);
    bool lowy = (qy - c_bnd[qcy]) < (c_bnd[qcy + 1] - qy);
    bool lowz = (qz - c_bnd[qcz]) < (c_bnd[qcz + 1] - qz);
    int x0 = max(qcx - (lowx ? 2 : 1), 0), x1 = min(qcx + (lowx ? 1 : 2), GD - 1);
    int wy0 = qcy - (lowy ? 2 : 1);   // unclamped (OOB rows get len 0)
    int wz0 = qcz - (lowz ? 2 : 1);
    int y0 = max(wy0, 0), y1 = min(qcy + (lowy ? 1 : 2), GD - 1);
    int z0 = max(wz0, 0), z1 = min(qcz + (lowz ? 1 : 2), GD - 1);

    scan_runs(x0, x1, wy0, 4, wz0, 16, qx, qy, qz, q2, pts, ids, offs, lane,
              bd1, bi1, bd2, bi2);

    float ub2 = warp_ub2(bd1, bd2);
    if (!term_ok_w(x0, x1, y0, y1, z0, z1, qx, qy, qz, ub2)) {
        // Phase 2: 5x5x5 box (25 runs; overlap deduped by id)
        int X0 = max(qcx - 2, 0), X1 = min(qcx + 2, GD - 1);
        scan_runs(X0, X1, qcy - 2, 5, qcz - 2, 25, qx, qy, qz, q2,
                  pts, ids, offs, lane, bd1, bi1, bd2, bi2);

        ub2 = warp_ub2(bd1, bd2);
        int Y0 = max(qcy - 2, 0), Y1 = min(qcy + 2, GD - 1);
        int Z0 = max(qcz - 2, 0), Z1 = min(qcz + 2, GD - 1);
        if (!term_ok_w(X0, X1, Y0, Y1, Z0, Z1, qx, qy, qz, ub2)) {
            // Phase 3: bounded fallback — full warp-parallel brute force
            for (int p = lane; p < HALF; p += 32) {
                float d2 = score(qx, qy, qz, q2, pts[p]);
                if (d2 <= bd2) ins2(d2, ids[p], bd1, bi1, bd2, bi2);
            }
        }
    }

    // final exact top-2 (u64 keys; stable-comparator order; key-dedup)
    u64 k1 = (bi1 == 0x7fffffff) ? KINF : (((u64)fenc32(bd1) << 32) | (u32)bi1);
    u64 k2 = (bi2 == 0x7fffffff) ? KINF : (((u64)fenc32(bd2) << 32) | (u32)bi2);
    warp_reduce_top2k(k1, k2);

    if (lane == 0)
        out[OFF_NIDX + (b << 13) + qi] = (float)(int)(u32)(k2 & 0xFFFFFFFFu);

    // Tail: re-zero histograms for next graph replay (4096 blocks x 8 ints)
    if (threadIdx.x < 8) {
        ((int*)g_cnt)[blockIdx.x * 8 + threadIdx.x] = 0;
    }
}

// ---------------------------------------------------------------------------
extern "C" void kernel_launch(void* const* d_in, const int* in_sizes, int n_in,
                              void* d_out, int out_size) {
    const float*  pc    = (const float*)d_in[0];
    const float4* feats = (const float4*)d_in[1];
    const int*    rnds  = (const int*)d_in[2];
    float*        out   = (float*)d_out;
    (void)in_sizes; (void)n_in; (void)out_size;

    const int total = BATCH * HALF * 8 + 2 * BATCH * HALF + NPTS;  // 344064
    gather_kernel<<<total / 256, 256>>>(pc, feats, rnds, out);

    scan_kernel<<<2 * BATCH, 1024>>>();
    scatter_kernel<<<(2 * BATCH * HALF + 255) / 256, 256>>>();

    // one warp per query: 32768 warps = 4096 blocks of 256 threads
    knn_kernel<<<BATCH * HALF * 32 / 256, 256>>>(out);
}

// round 16
// speedup vs baseline: 1.4348x; 1.4348x over previous
#include <cuda_runtime.h>

// Problem constants
#define BATCH   4
#define NPTS    16384
#define HALF    8192
#define FDIM    32
#define GD      16               // cells per axis (in CDF/u-space)
#define NC      (GD*GD*GD)       // 4096 cells per batch

typedef unsigned int u32;
typedef unsigned long long u64;

// Output layout (concatenated tuple, float32)
#define OFF_VPC   0
#define OFF_VFEAT (BATCH * HALF * 3)                  // 98304
#define OFF_NIDX  (OFF_VFEAT + BATCH * HALF * FDIM)   // 1146880
#define OFF_RNDS  (OFF_NIDX + BATCH * HALF)           // 1179648

// Cell boundaries in x-space: standard normal quantiles Phi^-1(i/16).
__constant__ float c_bnd[GD + 1] = {
    -1e30f,
    -1.5341206f, -1.1503494f, -0.8871466f, -0.6744898f,
    -0.4887764f, -0.3186394f, -0.1573107f,  0.0f,
     0.1573107f,  0.3186394f,  0.4887764f,  0.6744898f,
     0.8871466f,  1.1503494f,  1.5341206f,
     1e30f
};

// ---------------------------------------------------------------------------
// Scratch (device globals). Zero-initialized at module load; g_cnt re-zeroed
// by knn_a's tail, g_qcount by gather, each replay.
// ---------------------------------------------------------------------------
__device__ float4 g_valid[BATCH][HALF];
__device__ float4 g_query[BATCH][HALF];
__device__ int    g_pcell[BATCH][HALF];
__device__ int    g_qcell[BATCH][HALF];
__device__ int    g_cnt[2][BATCH][NC];
__device__ int    g_off[2][BATCH][NC+1];
__device__ int    g_cur[2][BATCH][NC];
__device__ float4 g_spt[BATCH][HALF];     // cell-sorted points (2x,2y,2z,p2)
__device__ int    g_sid[BATCH][HALF];     // original point index
__device__ float4 g_sq[BATCH][HALF];      // cell-sorted queries (x,y,z,q2)
__device__ int    g_sqid[BATCH][HALF];
__device__ int    g_sqc[BATCH][HALF];
__device__ int    g_qlist[BATCH * HALF];  // unresolved (phase-B) query slots
__device__ int    g_qcount;

// ||v||^2 left-to-right, no FMA contraction (match jax fp32 semantics)
__device__ __forceinline__ float sq3(float x, float y, float z) {
    return __fadd_rn(__fadd_rn(__fmul_rn(x, x), __fmul_rn(y, y)), __fmul_rn(z, z));
}

__device__ __forceinline__ int axis_cell(float x) {
    float u = __fmaf_rn(erff(x * 0.70710678f), 0.5f, 0.5f);
    int c = (int)(u * (float)GD);
    return max(0, min(GD - 1, c));
}
__device__ __forceinline__ int cell_of(float x, float y, float z) {
    return (axis_cell(z) * GD + axis_cell(y)) * GD + axis_cell(x);
}

// Order-preserving float->u32 encode (monotone incl. +inf)
__device__ __forceinline__ u32 fenc32(float f) {
    u32 u = __float_as_uint(f);
    return u ^ ((u32)((int)u >> 31) | 0x80000000u);
}
__device__ __forceinline__ float fdec32(u32 e) {
    return __uint_as_float((e & 0x80000000u) ? (e ^ 0x80000000u) : ~e);
}

__device__ __forceinline__ bool lt2(float d, int i, float e, int j) {
    return d < e || (d == e && i < j);
}

// Insert candidate (d, i) into per-lane sorted top-2, deduping by id.
__device__ __forceinline__ void ins2(float d, int i,
                                     float& bd1, int& bi1,
                                     float& bd2, int& bi2) {
    if (i == bi1 || i == bi2) return;
    if (lt2(d, i, bd1, bi1)) {
        bd2 = bd1; bi2 = bi1; bd1 = d; bi1 = i;
    } else if (lt2(d, i, bd2, bi2)) {
        bd2 = d; bi2 = i;
    }
}

// Final exact top-2 via u64 keys: key=(enc(d)<<32)|id; u64 order == stable
// top_k comparator; same id => identical key => duplicate collapse.
#define KINF (((u64)0xFF800000u << 32) | 0xFFFFFFFFu)
__device__ __forceinline__ void warp_reduce_top2k(u64& k1, u64& k2) {
    u64 k1g = k1;
#pragma unroll
    for (int o = 16; o > 0; o >>= 1)
        k1g = min(k1g, __shfl_xor_sync(0xFFFFFFFFu, k1g, o));
    u64 cand = (k1 == k1g) ? k2 : k1;
#pragma unroll
    for (int o = 16; o > 0; o >>= 1)
        cand = min(cand, __shfl_xor_sync(0xFFFFFFFFu, cand, o));
    k1 = k1g; k2 = cand;
}

// Conservative UPPER bound on global bd2 via 2x hardware REDUX (safe:
// equal-distance collisions only raise it).
__device__ __forceinline__ float warp_ub2(float bd1, float bd2) {
    u32 e1 = fenc32(bd1);
    u32 m1 = __reduce_min_sync(0xFFFFFFFFu, e1);
    u32 c = (e1 == m1) ? fenc32(bd2) : e1;
    u32 m2 = __reduce_min_sync(0xFFFFFFFFu, c);
    return fdec32(m2);
}

__device__ __forceinline__ float score(float qx, float qy, float qz, float q2,
                                       float4 P) {
    float dot2 = __fadd_rn(__fadd_rn(__fmul_rn(qx, P.x), __fmul_rn(qy, P.y)),
                           __fmul_rn(qz, P.z));
    return __fsub_rn(__fadd_rn(q2, P.w), dot2);
}

// pack per-lane float top-2 into u64 keys + exact reduce; returns 2nd index
__device__ __forceinline__ int final_top2_idx(float bd1, int bi1,
                                              float bd2, int bi2) {
    u64 k1 = (bi1 == 0x7fffffff) ? KINF : (((u64)fenc32(bd1) << 32) | (u32)bi1);
    u64 k2 = (bi2 == 0x7fffffff) ? KINF : (((u64)fenc32(bd2) << 32) | (u32)bi2);
    warp_reduce_top2k(k1, k2);
    return (int)(u32)(k2 & 0xFFFFFFFFu);
}

// ---------------------------------------------------------------------------
// Generic window scan: flat-index chunks over NR contiguous runs (rows),
// SEARCH_STEP-deep binary search for run assignment. Full lane utilization.
// y0/z0 may be unclamped (OOB rows get len 0). x0/x1 must be clamped.
// ---------------------------------------------------------------------------
template <int NYW, int NR, int SEARCH0>
__device__ __forceinline__ void scan_window(int x0, int x1, int y0, int z0,
                                            float qx, float qy, float qz,
                                            float q2,
                                            const float4* __restrict__ pts,
                                            const int* __restrict__ ids,
                                            const int* __restrict__ offs,
                                            int lane,
                                            float& bd1, int& bi1,
                                            float& bd2, int& bi2) {
    int p0 = 0, len = 0;
    if (lane < NR) {
        int cy = y0 + lane % NYW;
        int cz = z0 + lane / NYW;
        if (cy >= 0 && cy < GD && cz >= 0 && cz < GD) {
            int rowbase = (cz * GD + cy) * GD;
            p0 = __ldg(&offs[rowbase + x0]);
            len = __ldg(&offs[rowbase + x1 + 1]) - p0;
        }
    }
    // warp inclusive scan of len
    int inc = len;
#pragma unroll
    for (int o = 1; o < 32; o <<= 1) {
        int v = __shfl_up_sync(0xFFFFFFFFu, inc, o);
        if (lane >= o) inc += v;
    }
    int excl = inc - len;
    int T = __shfl_sync(0xFFFFFFFFu, inc, NR - 1);

    for (int base = 0; base < T; base += 32) {
        int c = base + lane;
        bool active = c < T;
        int cc = active ? c : (T - 1);
        int lo = 0;
#pragma unroll
        for (int step = SEARCH0; step > 0; step >>= 1) {
            int mid = lo + step;
            int v = __shfl_sync(0xFFFFFFFFu, excl, min(mid, 31));
            if (mid < NR && v <= cc) lo = mid;
        }
        int p = __shfl_sync(0xFFFFFFFFu, p0, lo) +
                (cc - __shfl_sync(0xFFFFFFFFu, excl, lo));
        float4 P = pts[p];
        if (active) {
            float d2 = score(qx, qy, qz, q2, P);
            if (d2 <= bd2) ins2(d2, ids[p], bd1, bi1, bd2, bi2);
        }
    }
}

// warp-uniform: can any cell outside [x0..x1]x[y0..y1]x[z0..z1] beat ub2?
__device__ __forceinline__ bool term_ok_w(int x0, int x1, int y0, int y1,
                                          int z0, int z1,
                                          float qx, float qy, float qz,
                                          float ub2) {
    const float INF = __int_as_float(0x7f800000);
    if (!(ub2 < INF)) return false;
    float lb = INF;
    if (x0 > 0)      lb = fminf(lb, qx - c_bnd[x0]);
    if (x1 < GD - 1) lb = fminf(lb, c_bnd[x1 + 1] - qx);
    if (y0 > 0)      lb = fminf(lb, qy - c_bnd[y0]);
    if (y1 < GD - 1) lb = fminf(lb, c_bnd[y1 + 1] - qy);
    if (z0 > 0)      lb = fminf(lb, qz - c_bnd[z0]);
    if (z1 < GD - 1) lb = fminf(lb, c_bnd[z1 + 1] - qz);
    float lba = fmaxf(lb - 1e-5f, 0.0f);
    return lba * lba > ub2 * 1.001f + 1e-4f;
}

// ---------------------------------------------------------------------------
// K1 (launch 0): gathers + binning + histogram (+ reset phase-B queue count)
// ---------------------------------------------------------------------------
__global__ void gather_kernel(const float* __restrict__ pc,
                              const float4* __restrict__ feats4,
                              const int* __restrict__ rnds,
                              float* __restrict__ out) {
    int i = blockIdx.x * blockDim.x + threadIdx.x;
    if (i == 0) g_qcount = 0;   // reset queue for this replay
    const int WF = BATCH * HALF * 8;
    const int WP = BATCH * HALF;

    if (i < WF) {
        int c = i & 7;
        int t = (i >> 3) & (HALF - 1);
        int b = i >> 16;
        int v = rnds[t];
        float4 val = feats4[(b * NPTS + v) * 8 + c];
        ((float4*)(out + OFF_VFEAT))[(b * HALF + t) * 8 + c] = val;
        return;
    }
    i -= WF;
    if (i < WP) {
        int t = i & (HALF - 1);
        int b = i >> 13;
        int v = rnds[t];
        int base = (b * NPTS + v) * 3;
        float x = pc[base + 0], y = pc[base + 1], z = pc[base + 2];
        int ob = OFF_VPC + (b * HALF + t) * 3;
        out[ob + 0] = x; out[ob + 1] = y; out[ob + 2] = z;
        g_valid[b][t] = make_float4(2.0f * x, 2.0f * y, 2.0f * z, sq3(x, y, z));
        int cid = cell_of(x, y, z);
        g_pcell[b][t] = cid;
        atomicAdd(&g_cnt[0][b][cid], 1);
        return;
    }
    i -= WP;
    if (i < WP) {
        int t = i & (HALF - 1);
        int b = i >> 13;
        int v = rnds[HALF + t];
        int base = (b * NPTS + v) * 3;
        float x = pc[base + 0], y = pc[base + 1], z = pc[base + 2];
        g_query[b][t] = make_float4(x, y, z, sq3(x, y, z));
        int cid = cell_of(x, y, z);
        g_qcell[b][t] = cid;
        atomicAdd(&g_cnt[1][b][cid], 1);
        return;
    }
    i -= WP;
    if (i < NPTS) out[OFF_RNDS + i] = (float)rnds[i];
}

// ---------------------------------------------------------------------------
// K2 (launch 1): exclusive scan via two-level warp shuffle scan
// ---------------------------------------------------------------------------
__global__ void __launch_bounds__(1024) scan_kernel() {
    int kind = blockIdx.x >> 2;
    int b = blockIdx.x & 3;
    const int CPT = NC / 1024;  // 4
    int tid = threadIdx.x;
    int lane = tid & 31;
    int wid = tid >> 5;

    int loc[CPT];
    int s = 0;
    const int* cnt = g_cnt[kind][b];
#pragma unroll
    for (int j = 0; j < CPT; ++j) { loc[j] = s; s += cnt[tid * CPT + j]; }

    int inc = s;
#pragma unroll
    for (int o = 1; o < 32; o <<= 1) {
        int v = __shfl_up_sync(0xFFFFFFFFu, inc, o);
        if (lane >= o) inc += v;
    }
    __shared__ int wsum[32];
    if (lane == 31) wsum[wid] = inc;
    __syncthreads();
    if (wid == 0) {
        int v = wsum[lane];
        int wi = v;
#pragma unroll
        for (int o = 1; o < 32; o <<= 1) {
            int u = __shfl_up_sync(0xFFFFFFFFu, wi, o);
            if (lane >= o) wi += u;
        }
        wsum[lane] = wi - v;
    }
    __syncthreads();
    int base = wsum[wid] + (inc - s);

    int* off_arr = g_off[kind][b];
    int* cur_arr = g_cur[kind][b];
#pragma unroll
    for (int j = 0; j < CPT; ++j) {
        int v = base + loc[j];
        off_arr[tid * CPT + j] = v;
        cur_arr[tid * CPT + j] = v;
    }
    if (tid == 1023) off_arr[NC] = base + s;
}

// ---------------------------------------------------------------------------
// K3 (launch 2): scatter into cell-sorted order
// ---------------------------------------------------------------------------
__global__ void scatter_kernel() {
    int i = blockIdx.x * blockDim.x + threadIdx.x;
    if (i >= 2 * BATCH * HALF) return;
    int kind = i >> 15;
    int b = (i >> 13) & (BATCH - 1);
    int t = i & (HALF - 1);
    if (kind == 0) {
        int cid = g_pcell[b][t];
        int pos = atomicAdd(&g_cur[0][b][cid], 1);
        g_spt[b][pos] = g_valid[b][t];
        g_sid[b][pos] = t;
    } else {
        int cid = g_qcell[b][t];
        int pos = atomicAdd(&g_cur[1][b][cid], 1);
        g_sq[b][pos] = g_query[b][t];
        g_sqid[b][pos] = t;
        g_sqc[b][pos] = cid;
    }
}

// ---------------------------------------------------------------------------
// K4 (launch 3): phase A — uniform lean pass. Adaptive 4x4x4 window,
// flat-index chunks, REDUX term. Resolved queries write out; unresolved
// enqueue to g_qlist (each query owns its output slot => deterministic).
// ---------------------------------------------------------------------------
__global__ void __launch_bounds__(256) knn_a(float* __restrict__ out) {
    int w = (blockIdx.x * blockDim.x + threadIdx.x) >> 5;
    int lane = threadIdx.x & 31;
    int b = w >> 13;
    int s = w & (HALF - 1);

    float4 q = g_sq[b][s];
    int qi = g_sqid[b][s];
    int qc = g_sqc[b][s];
    const float qx = q.x, qy = q.y, qz = q.z, q2 = q.w;

    int qcx = qc & (GD - 1);
    int qcy = (qc >> 4) & (GD - 1);
    int qcz = qc >> 8;

    const float INF = __int_as_float(0x7f800000);
    float bd1 = INF, bd2 = INF;
    int bi1 = 0x7fffffff, bi2 = 0x7fffffff;

    const float4* __restrict__ pts = g_spt[b];
    const int* __restrict__ ids = g_sid[b];
    const int* __restrict__ offs = g_off[0][b];

    // adaptive 4-cell window per axis, centered on query within its cell
    bool lowx = (qx - c_bnd[qcx]) < (c_bnd[qcx + 1] - qx);
    bool lowy = (qy - c_bnd[qcy]) < (c_bnd[qcy + 1] - qy);
    bool lowz = (qz - c_bnd[qcz]) < (c_bnd[qcz + 1] - qz);
    int x0 = max(qcx - (lowx ? 2 : 1), 0), x1 = min(qcx + (lowx ? 1 : 2), GD - 1);
    int wy0 = qcy - (lowy ? 2 : 1);          // unclamped; OOB rows len 0
    int wz0 = qcz - (lowz ? 2 : 1);
    int y0 = max(wy0, 0), y1 = min(qcy + (lowy ? 1 : 2), GD - 1);
    int z0 = max(wz0, 0), z1 = min(qcz + (lowz ? 1 : 2), GD - 1);

    scan_window<4, 16, 8>(x0, x1, wy0, wz0, qx, qy, qz, q2,
                          pts, ids, offs, lane, bd1, bi1, bd2, bi2);

    float ub2 = warp_ub2(bd1, bd2);
    if (term_ok_w(x0, x1, y0, y1, z0, z1, qx, qy, qz, ub2)) {
        int idx2 = final_top2_idx(bd1, bi1, bd2, bi2);
        if (lane == 0) out[OFF_NIDX + (b << 13) + qi] = (float)idx2;
    } else {
        if (lane == 0) {
            int pos = atomicAdd(&g_qcount, 1);
            g_qlist[pos] = w;    // (b, sorted-slot) packed as global warp id
        }
    }

    // Tail: re-zero histograms for next graph replay (4096 blocks x 8 ints)
    if (threadIdx.x < 8) {
        ((int*)g_cnt)[blockIdx.x * 8 + threadIdx.x] = 0;
    }
}

// ---------------------------------------------------------------------------
// K5 (launch 4): phase B — unresolved queries only. Fresh 5x5x5 box scan,
// term check, bounded brute-force fallback. Cross-stage duplicates collapse
// via u64 key-equality in the final reduce (R12-proven pattern).
// ---------------------------------------------------------------------------
__global__ void __launch_bounds__(256) knn_b(float* __restrict__ out) {
    int wslot = (blockIdx.x * blockDim.x + threadIdx.x) >> 5;
    int lane = threadIdx.x & 31;

    int nq = g_qcount;           // uniform read
    if (wslot >= nq) return;

    int w = g_qlist[wslot];
    int b = w >> 13;
    int s = w & (HALF - 1);

    float4 q = g_sq[b][s];
    int qi = g_sqid[b][s];
    int qc = g_sqc[b][s];
    const float qx = q.x, qy = q.y, qz = q.z, q2 = q.w;

    int qcx = qc & (GD - 1);
    int qcy = (qc >> 4) & (GD - 1);
    int qcz = qc >> 8;

    const float INF = __int_as_float(0x7f800000);
    float bd1 = INF, bd2 = INF;
    int bi1 = 0x7fffffff, bi2 = 0x7fffffff;

    const float4* __restrict__ pts = g_spt[b];
    const int* __restrict__ ids = g_sid[b];
    const int* __restrict__ offs = g_off[0][b];

    // 5x5x5 box (25 runs), fresh scan
    int X0 = max(qcx - 2, 0), X1 = min(qcx + 2, GD - 1);
    scan_window<5, 25, 16>(X0, X1, qcy - 2, qcz - 2, qx, qy, qz, q2,
                           pts, ids, offs, lane, bd1, bi1, bd2, bi2);

    float ub2 = warp_ub2(bd1, bd2);
    int Y0 = max(qcy - 2, 0), Y1 = min(qcy + 2, GD - 1);
    int Z0 = max(qcz - 2, 0), Z1 = min(qcz + 2, GD - 1);
    if (!term_ok_w(X0, X1, Y0, Y1, Z0, Z1, qx, qy, qz, ub2)) {
        // bounded fallback: warp-parallel brute force over all points
        for (int p = lane; p < HALF; p += 32) {
            float d2 = score(qx, qy, qz, q2, pts[p]);
            if (d2 <= bd2) ins2(d2, ids[p], bd1, bi1, bd2, bi2);
        }
    }

    int idx2 = final_top2_idx(bd1, bi1, bd2, bi2);
    if (lane == 0) out[OFF_NIDX + (b << 13) + qi] = (float)idx2;
}

// ---------------------------------------------------------------------------
extern "C" void kernel_launch(void* const* d_in, const int* in_sizes, int n_in,
                              void* d_out, int out_size) {
    const float*  pc    = (const float*)d_in[0];
    const float4* feats = (const float4*)d_in[1];
    const int*    rnds  = (const int*)d_in[2];
    float*        out   = (float*)d_out;
    (void)in_sizes; (void)n_in; (void)out_size;

    const int total = BATCH * HALF * 8 + 2 * BATCH * HALF + NPTS;  // 344064
    gather_kernel<<<total / 256, 256>>>(pc, feats, rnds, out);

    scan_kernel<<<2 * BATCH, 1024>>>();
    scatter_kernel<<<(2 * BATCH * HALF + 255) / 256, 256>>>();

    // phase A: one warp per query (4096 blocks); phase B: worst-case grid,
    // warps beyond the queue count exit immediately.
    knn_a<<<BATCH * HALF * 32 / 256, 256>>>(out);
    knn_b<<<BATCH * HALF * 32 / 256, 256>>>(out);
}